// round 1
// baseline (speedup 1.0000x reference)
#include <cuda_runtime.h>
#include <math.h>

// Problem constants (B=2, S=2048, Dm=768, I=1536, N=16, R=48, K=4)
#define BSZ 2
#define SEQ 2048
#define DM 768
#define II 1536
#define NST 16
#define RR 48
#define MROWS (BSZ * SEQ)          // 4096
#define EPROJ 80                   // R + 2N

// ---------------- scratch (no allocations allowed) ----------------
__device__ float g_proj [(size_t)MROWS * 2 * II];   // [B*S, 2I]  in_proj out
__device__ float g_h    [(size_t)MROWS * II];       // [B*S, I]   conv+silu
__device__ float g_ssmp [(size_t)MROWS * EPROJ];    // [B*S, 80]  x_proj out
__device__ float g_xpart[(size_t)8 * MROWS * EPROJ];// split-K partials
__device__ float g_dt   [(size_t)MROWS * II];       // [B*S, I]   softplus(dt)
__device__ float g_y    [(size_t)MROWS * II];       // [B*S, I]   scan out (epilogue fused)

// ---------------- generic NT SGEMM: C[M,N] = A[M,K] * B[N,K]^T ----------------
// 128x128 tile, BK=8, 256 threads, 8x8 per thread. Requires M % 128 == 0,
// kCount % 8 == 0, 16B-aligned rows (true for all call sites). N guarded.
// epi: 0 = plain store, 1 = softplus(acc + bias[n]).
// Split-K: blockIdx.z picks k-chunk of kCount, writes slice z (cSlice elems apart).
__global__ __launch_bounds__(256) void sgemm_nt(
    const float* __restrict__ A, const float* __restrict__ B,
    float* __restrict__ C, const float* __restrict__ bias,
    int N, int lda, int ldb, int ldc,
    int kCount, size_t cSlice, int epi)
{
    __shared__ float As[8][128];
    __shared__ float Bs[8][128];
    const int tid  = threadIdx.x;
    const int tx   = tid & 15, ty = tid >> 4;
    const int bm   = blockIdx.y * 128;
    const int bn   = blockIdx.x * 128;
    const int arow = tid >> 1;
    const int acol = (tid & 1) * 4;
    const int kOff = blockIdx.z * kCount;

    float acc[8][8];
#pragma unroll
    for (int i = 0; i < 8; i++)
#pragma unroll
        for (int j = 0; j < 8; j++) acc[i][j] = 0.f;

    const float* Aptr = A + (size_t)(bm + arow) * lda + kOff + acol;
    const int brow = bn + arow;
    const bool bok = brow < N;
    const float* Bptr = B + (size_t)(bok ? brow : 0) * ldb + kOff + acol;

    for (int k0 = 0; k0 < kCount; k0 += 8) {
        float4 av = *(const float4*)(Aptr + k0);
        float4 bv = bok ? *(const float4*)(Bptr + k0)
                        : make_float4(0.f, 0.f, 0.f, 0.f);
        As[acol + 0][arow] = av.x; As[acol + 1][arow] = av.y;
        As[acol + 2][arow] = av.z; As[acol + 3][arow] = av.w;
        Bs[acol + 0][arow] = bv.x; Bs[acol + 1][arow] = bv.y;
        Bs[acol + 2][arow] = bv.z; Bs[acol + 3][arow] = bv.w;
        __syncthreads();
#pragma unroll
        for (int k = 0; k < 8; k++) {
            float a[8], b[8];
#pragma unroll
            for (int i = 0; i < 8; i++) a[i] = As[k][ty + 16 * i];
#pragma unroll
            for (int j = 0; j < 8; j++) b[j] = Bs[k][tx + 16 * j];
#pragma unroll
            for (int i = 0; i < 8; i++)
#pragma unroll
                for (int j = 0; j < 8; j++)
                    acc[i][j] = fmaf(a[i], b[j], acc[i][j]);
        }
        __syncthreads();
    }

    float* Cout = C + (size_t)blockIdx.z * cSlice;
#pragma unroll
    for (int i = 0; i < 8; i++) {
        const int gm = bm + ty + 16 * i;
#pragma unroll
        for (int j = 0; j < 8; j++) {
            const int gn = bn + tx + 16 * j;
            if (gn < N) {
                float v = acc[i][j];
                if (epi == 1) {
                    v += bias[gn];
                    v = (v > 20.f) ? v : log1pf(__expf(v));
                }
                Cout[(size_t)gm * ldc + gn] = v;
            }
        }
    }
}

// ---------------- causal depthwise conv1d (K=4) + bias + SiLU ----------------
__global__ void conv_silu_kernel(const float* __restrict__ proj,
                                 const float* __restrict__ cw,
                                 const float* __restrict__ cb,
                                 float* __restrict__ h)
{
    const int idx = blockIdx.x * blockDim.x + threadIdx.x; // b*S*I + s*I + i
    if (idx >= BSZ * SEQ * II) return;
    const int i = idx % II;
    const int s = (idx / II) % SEQ;
    const int b = idx / (II * SEQ);
    const float* base = proj + (size_t)b * SEQ * 2 * II + i;
    float acc = cb[i];
#pragma unroll
    for (int k = 0; k < 4; k++) {
        const int sp = s - 3 + k;
        if (sp >= 0) acc = fmaf(base[(size_t)sp * 2 * II], cw[i * 4 + k], acc);
    }
    h[idx] = acc / (1.f + __expf(-acc)); // silu
}

// ---------------- split-K partial reduction (deterministic) ----------------
__global__ void reduce8_kernel(float* __restrict__ out,
                               const float* __restrict__ part, int n)
{
    const int idx = blockIdx.x * blockDim.x + threadIdx.x;
    if (idx >= n) return;
    float s = 0.f;
#pragma unroll
    for (int z = 0; z < 8; z++) s += part[(size_t)z * n + idx];
    out[idx] = s;
}

// ---------------- selective scan + fused output epilogue ----------------
// warp handles 2 channels (16 lanes each, lane&15 = state index n).
// y[b,s,i] = (sum_n state*C + h*D) * silu(gate); dt last-step *= alpha;
// y last-step *= feature_gating.
__global__ __launch_bounds__(128) void scan_kernel(
    const float* __restrict__ dt, const float* __restrict__ h,
    const float* __restrict__ ssmp, const float* __restrict__ proj,
    const float* __restrict__ A_log, const float* __restrict__ Dw,
    const float* __restrict__ alpha, const float* __restrict__ fg,
    float* __restrict__ Y)
{
    const int warp = threadIdx.x >> 5;
    const int lane = threadIdx.x & 31;
    const int grp  = lane >> 4;
    const int n    = lane & 15;
    const int i    = (blockIdx.x * 4 + warp) * 2 + grp;
    const int b    = blockIdx.y;

    const float Ai  = -__expf(A_log[i * NST + n]);
    const float Di  = Dw[i];
    const float al  = alpha[i];
    const float fgv = fg[i];

    const float* dtp = dt   + (size_t)b * SEQ * II + i;
    const float* hp  = h    + (size_t)b * SEQ * II + i;
    const float* bp  = ssmp + (size_t)b * SEQ * EPROJ + RR + n;
    const float* cp  = ssmp + (size_t)b * SEQ * EPROJ + RR + NST + n;
    const float* gp  = proj + (size_t)b * SEQ * 2 * II + II + i;
    float*       yp  = Y    + (size_t)b * SEQ * II + i;

    float state = 0.f;
    for (int s = 0; s < SEQ; s++) {
        float dtv = dtp[(size_t)s * II];
        if (s == SEQ - 1) dtv *= al;
        const float hv = hp[(size_t)s * II];
        const float Bv = bp[(size_t)s * EPROJ];
        const float Cv = cp[(size_t)s * EPROJ];
        const float dA = __expf(Ai * dtv);
        state = fmaf(dA, state, dtv * Bv * hv);
        float p = state * Cv;
        p += __shfl_xor_sync(0xffffffffu, p, 8);
        p += __shfl_xor_sync(0xffffffffu, p, 4);
        p += __shfl_xor_sync(0xffffffffu, p, 2);
        p += __shfl_xor_sync(0xffffffffu, p, 1);
        if (n == 0) {
            const float gv = gp[(size_t)s * 2 * II];
            const float sg = gv / (1.f + __expf(-gv));
            float yv = (p + hv * Di) * sg;
            if (s == SEQ - 1) yv *= fgv;
            yp[(size_t)s * II] = yv;
        }
    }
}

// ---------------- launch ----------------
extern "C" void kernel_launch(void* const* d_in, const int* in_sizes, int n_in,
                              void* d_out, int out_size)
{
    const float* input   = (const float*)d_in[0];   // [B,S,Dm]
    const float* inw     = (const float*)d_in[1];   // [2I,Dm]
    const float* convw   = (const float*)d_in[2];   // [I,1,4]
    const float* convb   = (const float*)d_in[3];   // [I]
    const float* xw      = (const float*)d_in[4];   // [80,I]
    const float* dtw     = (const float*)d_in[5];   // [I,48]
    const float* dtb     = (const float*)d_in[6];   // [I]
    const float* A_log   = (const float*)d_in[7];   // [I,16]
    const float* Dw      = (const float*)d_in[8];   // [I]
    const float* outw    = (const float*)d_in[9];   // [Dm,I]
    const float* alpha   = (const float*)d_in[10];  // [I]
    const float* fg      = (const float*)d_in[11];  // [I]
    float* out = (float*)d_out;                     // [B,S,Dm]

    float *proj, *h, *ssmp, *xpart, *dt, *y;
    cudaGetSymbolAddress((void**)&proj,  g_proj);
    cudaGetSymbolAddress((void**)&h,     g_h);
    cudaGetSymbolAddress((void**)&ssmp,  g_ssmp);
    cudaGetSymbolAddress((void**)&xpart, g_xpart);
    cudaGetSymbolAddress((void**)&dt,    g_dt);
    cudaGetSymbolAddress((void**)&y,     g_y);

    // 1) in_proj: proj[4096,3072] = input[4096,768] @ inw[3072,768]^T
    sgemm_nt<<<dim3(2 * II / 128, MROWS / 128, 1), 256>>>(
        input, inw, proj, nullptr, 2 * II, DM, DM, 2 * II, DM, 0, 0);

    // 2) depthwise conv + SiLU -> h[4096,1536]
    {
        const int n = BSZ * SEQ * II;
        conv_silu_kernel<<<(n + 255) / 256, 256>>>(proj, convw, convb, h);
    }

    // 3) x_proj (skinny N=80): split-K(8) into partials, then reduce
    sgemm_nt<<<dim3(1, MROWS / 128, 8), 256>>>(
        h, xw, xpart, nullptr, EPROJ, II, II, EPROJ, II / 8,
        (size_t)MROWS * EPROJ, 0);
    {
        const int n = MROWS * EPROJ;
        reduce8_kernel<<<(n + 255) / 256, 256>>>(ssmp, xpart, n);
    }

    // 4) dt_proj + softplus: dt[4096,1536] = softplus(ssmp[:, :48] @ dtw^T + b)
    sgemm_nt<<<dim3(II / 128, MROWS / 128, 1), 256>>>(
        ssmp, dtw, dt, dtb, II, EPROJ, RR, II, RR, 0, 1);

    // 5) selective scan with fused gating epilogue -> y[4096,1536]
    scan_kernel<<<dim3(II / 8, BSZ), 128>>>(
        dt, h, ssmp, proj, A_log, Dw, alpha, fg, y);

    // 6) out_proj: out[4096,768] = y @ outw[768,1536]^T
    sgemm_nt<<<dim3(DM / 128, MROWS / 128, 1), 256>>>(
        y, outw, out, nullptr, DM, II, II, DM, II, 0, 0);
}

// round 3
// speedup vs baseline: 1.1648x; 1.1648x over previous
#include <cuda_runtime.h>
#include <cuda_bf16.h>
#include <math.h>
#include <stdint.h>

// Problem constants (B=2, S=2048, Dm=768, I=1536, N=16, R=48, K=4)
#define BSZ 2
#define SEQ 2048
#define DM 768
#define II 1536
#define NST 16
#define RR 48
#define MROWS (BSZ * SEQ)          // 4096
#define EPROJ 80                   // R + 2N
#define KPAD 64                    // padded K for dt_proj
#define XSPLIT 4                   // split-K factor for x_proj

// ---------------- scratch (no allocations allowed) ----------------
__device__ float g_proj [(size_t)MROWS * 2 * II];
__device__ float g_h    [(size_t)MROWS * II];
__device__ float g_ssmp [(size_t)MROWS * EPROJ];
__device__ float g_xpart[(size_t)XSPLIT * MROWS * EPROJ];
__device__ float g_dt   [(size_t)MROWS * II];

__device__ __nv_bfloat16 g_inh[(size_t)MROWS * DM],  g_inl[(size_t)MROWS * DM];
__device__ __nv_bfloat16 g_wih[(size_t)2 * II * DM], g_wil[(size_t)2 * II * DM];
__device__ __nv_bfloat16 g_hh [(size_t)MROWS * II],  g_hl [(size_t)MROWS * II];
__device__ __nv_bfloat16 g_xwh[(size_t)EPROJ * II],  g_xwl[(size_t)EPROJ * II];
__device__ __nv_bfloat16 g_ssh[(size_t)MROWS * KPAD],g_ssl[(size_t)MROWS * KPAD];
__device__ __nv_bfloat16 g_dwh[(size_t)II * KPAD],   g_dwl[(size_t)II * KPAD];
__device__ __nv_bfloat16 g_yh [(size_t)MROWS * II],  g_yl [(size_t)MROWS * II];
__device__ __nv_bfloat16 g_owh[(size_t)DM * II],     g_owl[(size_t)DM * II];

// ---------------- PTX helpers (arch-agnostic: sm_80+ features only) ----------
__device__ __forceinline__ uint32_t smem_u32(const void* p) {
    uint32_t a;
    asm("{ .reg .u64 t; cvta.to.shared.u64 t, %1; cvt.u32.u64 %0, t; }"
        : "=r"(a) : "l"(p));
    return a;
}
__device__ __forceinline__ void cp_async16(uint32_t dst, const void* src, unsigned bytes) {
    asm volatile("cp.async.cg.shared.global [%0], [%1], 16, %2;"
                 :: "r"(dst), "l"(src), "r"(bytes));
}
__device__ __forceinline__ void cp_commit() {
    asm volatile("cp.async.commit_group;");
}
__device__ __forceinline__ void cp_wait0() {
    asm volatile("cp.async.wait_group 0;");
}
__device__ __forceinline__ void ldm_x4(uint32_t* r, uint32_t addr) {
    asm volatile("ldmatrix.sync.aligned.m8n8.x4.shared.b16 {%0,%1,%2,%3}, [%4];"
                 : "=r"(r[0]), "=r"(r[1]), "=r"(r[2]), "=r"(r[3]) : "r"(addr));
}
__device__ __forceinline__ void mma_bf16(float* c, const uint32_t* a, const uint32_t* b) {
    asm volatile(
        "mma.sync.aligned.m16n8k16.row.col.f32.bf16.bf16.f32 "
        "{%0,%1,%2,%3}, {%4,%5,%6,%7}, {%8,%9}, {%0,%1,%2,%3};"
        : "+f"(c[0]), "+f"(c[1]), "+f"(c[2]), "+f"(c[3])
        : "r"(a[0]), "r"(a[1]), "r"(a[2]), "r"(a[3]), "r"(b[0]), "r"(b[1]));
}

// ---------------- bf16 hi/lo 3-term GEMM: C[M,N] = A[M,K] * B[N,K]^T ---------
// 128x128x32 tile, 256 threads, cp.async double buffer, warp-level MMA.
// epi: 0 plain store, 1 softplus(v + bias[n]).
#define APAD 40                         // bf16 elems per smem row (32 + 8 pad)
#define ROWB (APAD * 2)                 // 80 bytes per row
#define TILE_B (128 * ROWB)             // 10240 bytes
#define STAGE_B (4 * TILE_B)            // Ah, Al, Bh, Bl
#define GSMEM (2 * STAGE_B)             // 81920 bytes

__device__ __forceinline__ void tile_async(uint32_t dstBase,
                                           const __nv_bfloat16* src, int ld,
                                           int nrows, int tid) {
#pragma unroll
    for (int q = 0; q < 2; q++) {
        const int id = tid + 256 * q;          // 0..511
        const int row = id >> 2, ch = id & 3;
        const uint32_t dst = dstBase + row * ROWB + ch * 16;
        const int srow = (row < nrows) ? row : 0;
        const unsigned bytes = (row < nrows) ? 16u : 0u;
        cp_async16(dst, src + (size_t)srow * ld + ch * 8, bytes);
    }
}

__global__ __launch_bounds__(256) void gemm_bf3(
    const __nv_bfloat16* __restrict__ Ah, const __nv_bfloat16* __restrict__ Al,
    const __nv_bfloat16* __restrict__ Bh, const __nv_bfloat16* __restrict__ Bl,
    float* __restrict__ C, const float* __restrict__ bias,
    int N, int lda, int ldb, int ldc, int nit, size_t cSlice, int epi)
{
    extern __shared__ char smem[];
    const uint32_t sbase = smem_u32(smem);
    const int tid = threadIdx.x;
    const int lane = tid & 31;
    const int wid = tid >> 5;
    const int wm = wid & 3;                 // 0..3 -> 32-row band
    const int wn = wid >> 2;                // 0..1 -> 64-col band
    const int bm = blockIdx.y * 128;
    const int bn = blockIdx.x * 128;
    const int nB = min(128, N - bn);
    const int kOff = blockIdx.z * nit * 32;

    const __nv_bfloat16* pAh = Ah + (size_t)bm * lda + kOff;
    const __nv_bfloat16* pAl = Al + (size_t)bm * lda + kOff;
    const __nv_bfloat16* pBh = Bh + (size_t)bn * ldb + kOff;
    const __nv_bfloat16* pBl = Bl + (size_t)bn * ldb + kOff;

    float acc[2][8][4];
#pragma unroll
    for (int m = 0; m < 2; m++)
#pragma unroll
        for (int n = 0; n < 8; n++)
#pragma unroll
            for (int v = 0; v < 4; v++) acc[m][n][v] = 0.f;

    // prologue: stage 0
    tile_async(sbase + 0 * TILE_B, pAh, lda, 128, tid);
    tile_async(sbase + 1 * TILE_B, pAl, lda, 128, tid);
    tile_async(sbase + 2 * TILE_B, pBh, ldb, nB,  tid);
    tile_async(sbase + 3 * TILE_B, pBl, ldb, nB,  tid);
    cp_commit();

    // per-lane ldmatrix offsets (within a tile, before k-step column shift)
    const uint32_t aOff =
        (uint32_t)((wm * 32 + (lane & 15)) * ROWB + ((lane >> 4) << 3) * 2);
    const uint32_t bOff =
        (uint32_t)((wn * 64 + ((lane >> 4) << 3) + (lane & 7)) * ROWB +
                   (((lane >> 3) & 1) << 3) * 2);

    for (int it = 0; it < nit; it++) {
        cp_wait0();
        __syncthreads();
        if (it + 1 < nit) {
            const uint32_t st = sbase + ((it + 1) & 1) * STAGE_B;
            const int k0 = (it + 1) * 32;
            tile_async(st + 0 * TILE_B, pAh + k0, lda, 128, tid);
            tile_async(st + 1 * TILE_B, pAl + k0, lda, 128, tid);
            tile_async(st + 2 * TILE_B, pBh + k0, ldb, nB,  tid);
            tile_async(st + 3 * TILE_B, pBl + k0, ldb, nB,  tid);
            cp_commit();
        }
        const uint32_t st = sbase + (it & 1) * STAGE_B;
#pragma unroll
        for (int ks = 0; ks < 2; ks++) {
            const uint32_t kshift = ks * 32;   // 16 bf16 = 32 bytes
            uint32_t a_hi[2][4], a_lo[2][4];
#pragma unroll
            for (int m = 0; m < 2; m++) {
                const uint32_t off = aOff + (uint32_t)(m * 16 * ROWB) + kshift;
                ldm_x4(a_hi[m], st + 0 * TILE_B + off);
                ldm_x4(a_lo[m], st + 1 * TILE_B + off);
            }
#pragma unroll
            for (int u = 0; u < 8; u += 2) {
                const uint32_t off = bOff + (uint32_t)(u * 8 * ROWB) + kshift;
                uint32_t bh[4], bl[4];
                ldm_x4(bh, st + 2 * TILE_B + off);
                ldm_x4(bl, st + 3 * TILE_B + off);
#pragma unroll
                for (int m = 0; m < 2; m++) {
                    mma_bf16(acc[m][u],     a_hi[m], bh);
                    mma_bf16(acc[m][u],     a_hi[m], bl);
                    mma_bf16(acc[m][u],     a_lo[m], bh);
                    mma_bf16(acc[m][u + 1], a_hi[m], bh + 2);
                    mma_bf16(acc[m][u + 1], a_hi[m], bl + 2);
                    mma_bf16(acc[m][u + 1], a_lo[m], bh + 2);
                }
            }
        }
    }

    // epilogue: direct global stores (c0,c1 @ row, c2,c3 @ row+8)
    float* Co = C + (size_t)blockIdx.z * cSlice;
    const int r0 = bm + wm * 32 + (lane >> 2);
    const int c0 = bn + wn * 64 + (lane & 3) * 2;
#pragma unroll
    for (int m = 0; m < 2; m++) {
#pragma unroll
        for (int n = 0; n < 8; n++) {
            const int gc = c0 + n * 8;
            if (gc < N) {
#pragma unroll
                for (int half = 0; half < 2; half++) {
                    const int gr = r0 + m * 16 + half * 8;
                    float v0 = acc[m][n][half * 2 + 0];
                    float v1 = acc[m][n][half * 2 + 1];
                    if (epi == 1) {
                        v0 += bias[gc];
                        v1 += bias[gc + 1];
                        v0 = (v0 > 20.f) ? v0 : log1pf(__expf(v0));
                        v1 = (v1 > 20.f) ? v1 : log1pf(__expf(v1));
                    }
                    Co[(size_t)gr * ldc + gc]     = v0;
                    Co[(size_t)gr * ldc + gc + 1] = v1;
                }
            }
        }
    }
}

// ---------------- fp32 -> bf16 hi/lo split ----------------
__device__ __forceinline__ void split2(float x, __nv_bfloat16& h, __nv_bfloat16& l) {
    h = __float2bfloat16(x);
    l = __float2bfloat16(x - __bfloat162float(h));
}
__global__ void cvt_split(const float* __restrict__ src,
                          __nv_bfloat16* __restrict__ hi, __nv_bfloat16* __restrict__ lo,
                          int rows, int scols, int dcols, int ccols)
{
    const int idx = blockIdx.x * blockDim.x + threadIdx.x;
    if (idx >= rows * dcols) return;
    const int r = idx / dcols, c = idx % dcols;
    float x = (c < ccols) ? src[(size_t)r * scols + c] : 0.f;
    __nv_bfloat16 h, l; split2(x, h, l);
    hi[idx] = h; lo[idx] = l;
}

// ---------------- causal depthwise conv1d (K=4) + bias + SiLU + split --------
__global__ void conv_silu_kernel(const float* __restrict__ proj,
                                 const float* __restrict__ cw,
                                 const float* __restrict__ cb,
                                 float* __restrict__ h,
                                 __nv_bfloat16* __restrict__ hh,
                                 __nv_bfloat16* __restrict__ hl)
{
    const int idx = blockIdx.x * blockDim.x + threadIdx.x;
    if (idx >= BSZ * SEQ * II) return;
    const int i = idx % II;
    const int s = (idx / II) % SEQ;
    const int b = idx / (II * SEQ);
    const float* base = proj + (size_t)b * SEQ * 2 * II + i;
    float acc = cb[i];
#pragma unroll
    for (int k = 0; k < 4; k++) {
        const int sp = s - 3 + k;
        if (sp >= 0) acc = fmaf(base[(size_t)sp * 2 * II], cw[i * 4 + k], acc);
    }
    const float v = acc / (1.f + __expf(-acc));
    h[idx] = v;
    __nv_bfloat16 vh, vl; split2(v, vh, vl);
    hh[idx] = vh; hl[idx] = vl;
}

// ---------------- split-K partial reduction (deterministic) ----------------
__global__ void reduce4_kernel(float* __restrict__ out,
                               const float* __restrict__ part, int n)
{
    const int idx = blockIdx.x * blockDim.x + threadIdx.x;
    if (idx >= n) return;
    float s = 0.f;
#pragma unroll
    for (int z = 0; z < XSPLIT; z++) s += part[(size_t)z * n + idx];
    out[idx] = s;
}

// ---------------- selective scan + fused output epilogue ----------------
__global__ __launch_bounds__(128) void scan_kernel(
    const float* __restrict__ dt, const float* __restrict__ h,
    const float* __restrict__ ssmp, const float* __restrict__ proj,
    const float* __restrict__ A_log, const float* __restrict__ Dw,
    const float* __restrict__ alpha, const float* __restrict__ fg,
    __nv_bfloat16* __restrict__ Yh, __nv_bfloat16* __restrict__ Yl)
{
    const int warp = threadIdx.x >> 5;
    const int lane = threadIdx.x & 31;
    const int grp  = lane >> 4;
    const int n    = lane & 15;
    const int i    = (blockIdx.x * 4 + warp) * 2 + grp;
    const int b    = blockIdx.y;

    const float Ai  = -__expf(A_log[i * NST + n]);
    const float Di  = Dw[i];
    const float al  = alpha[i];
    const float fgv = fg[i];

    const float* dtp = dt   + (size_t)b * SEQ * II + i;
    const float* hp  = h    + (size_t)b * SEQ * II + i;
    const float* bp  = ssmp + (size_t)b * SEQ * EPROJ + RR + n;
    const float* cp  = ssmp + (size_t)b * SEQ * EPROJ + RR + NST + n;
    const float* gp  = proj + (size_t)b * SEQ * 2 * II + II + i;
    const size_t yo  = (size_t)b * SEQ * II + i;

    float state = 0.f;
    for (int s = 0; s < SEQ; s++) {
        float dtv = dtp[(size_t)s * II];
        if (s == SEQ - 1) dtv *= al;
        const float hv = hp[(size_t)s * II];
        const float Bv = bp[(size_t)s * EPROJ];
        const float Cv = cp[(size_t)s * EPROJ];
        const float dA = __expf(Ai * dtv);
        state = fmaf(dA, state, dtv * Bv * hv);
        float p = state * Cv;
        p += __shfl_xor_sync(0xffffffffu, p, 8);
        p += __shfl_xor_sync(0xffffffffu, p, 4);
        p += __shfl_xor_sync(0xffffffffu, p, 2);
        p += __shfl_xor_sync(0xffffffffu, p, 1);
        if (n == 0) {
            const float gv = gp[(size_t)s * 2 * II];
            const float sg = gv / (1.f + __expf(-gv));
            float yv = (p + hv * Di) * sg;
            if (s == SEQ - 1) yv *= fgv;
            __nv_bfloat16 vh, vl; split2(yv, vh, vl);
            Yh[yo + (size_t)s * II] = vh;
            Yl[yo + (size_t)s * II] = vl;
        }
    }
}

// ---------------- launch ----------------
extern "C" void kernel_launch(void* const* d_in, const int* in_sizes, int n_in,
                              void* d_out, int out_size)
{
    const float* input   = (const float*)d_in[0];
    const float* inw     = (const float*)d_in[1];
    const float* convw   = (const float*)d_in[2];
    const float* convb   = (const float*)d_in[3];
    const float* xw      = (const float*)d_in[4];
    const float* dtw     = (const float*)d_in[5];
    const float* dtb     = (const float*)d_in[6];
    const float* A_log   = (const float*)d_in[7];
    const float* Dw      = (const float*)d_in[8];
    const float* outw    = (const float*)d_in[9];
    const float* alpha   = (const float*)d_in[10];
    const float* fg      = (const float*)d_in[11];
    float* out = (float*)d_out;

    float *proj, *h, *ssmp, *xpart, *dt;
    __nv_bfloat16 *inh,*inl,*wih,*wil,*hh,*hl,*xwh,*xwl,*ssh,*ssl,*dwh,*dwl,*yh,*yl,*owh,*owl;
    cudaGetSymbolAddress((void**)&proj,  g_proj);
    cudaGetSymbolAddress((void**)&h,     g_h);
    cudaGetSymbolAddress((void**)&ssmp,  g_ssmp);
    cudaGetSymbolAddress((void**)&xpart, g_xpart);
    cudaGetSymbolAddress((void**)&dt,    g_dt);
    cudaGetSymbolAddress((void**)&inh, g_inh); cudaGetSymbolAddress((void**)&inl, g_inl);
    cudaGetSymbolAddress((void**)&wih, g_wih); cudaGetSymbolAddress((void**)&wil, g_wil);
    cudaGetSymbolAddress((void**)&hh,  g_hh);  cudaGetSymbolAddress((void**)&hl,  g_hl);
    cudaGetSymbolAddress((void**)&xwh, g_xwh); cudaGetSymbolAddress((void**)&xwl, g_xwl);
    cudaGetSymbolAddress((void**)&ssh, g_ssh); cudaGetSymbolAddress((void**)&ssl, g_ssl);
    cudaGetSymbolAddress((void**)&dwh, g_dwh); cudaGetSymbolAddress((void**)&dwl, g_dwl);
    cudaGetSymbolAddress((void**)&yh,  g_yh);  cudaGetSymbolAddress((void**)&yl,  g_yl);
    cudaGetSymbolAddress((void**)&owh, g_owh); cudaGetSymbolAddress((void**)&owl, g_owl);

    cudaFuncSetAttribute(gemm_bf3, cudaFuncAttributeMaxDynamicSharedMemorySize, GSMEM);

    auto cvt = [](const float* s, __nv_bfloat16* hi, __nv_bfloat16* lo,
                  int rows, int scols, int dcols, int ccols) {
        const int n = rows * dcols;
        cvt_split<<<(n + 255) / 256, 256>>>(s, hi, lo, rows, scols, dcols, ccols);
    };

    // operand splits for in_proj
    cvt(input, inh, inl, MROWS, DM, DM, DM);
    cvt(inw,   wih, wil, 2 * II, DM, DM, DM);

    // 1) in_proj: proj[4096,3072] = input @ inw^T   (K=768, 24 iters)
    gemm_bf3<<<dim3(2 * II / 128, MROWS / 128, 1), 256, GSMEM>>>(
        inh, inl, wih, wil, proj, nullptr, 2 * II, DM, DM, 2 * II, DM / 32, 0, 0);

    // 2) depthwise conv + SiLU -> h (fp32 + bf16 hi/lo)
    {
        const int n = BSZ * SEQ * II;
        conv_silu_kernel<<<(n + 255) / 256, 256>>>(proj, convw, convb, h, hh, hl);
    }

    // 3) x_proj: ssmp[4096,80] = h @ xw^T  (split-K x4 + reduce)
    cvt(xw, xwh, xwl, EPROJ, II, II, II);
    gemm_bf3<<<dim3(1, MROWS / 128, XSPLIT), 256, GSMEM>>>(
        hh, hl, xwh, xwl, xpart, nullptr, EPROJ, II, II, EPROJ,
        II / (XSPLIT * 32), (size_t)MROWS * EPROJ, 0);
    {
        const int n = MROWS * EPROJ;
        reduce4_kernel<<<(n + 255) / 256, 256>>>(ssmp, xpart, n);
    }

    // 4) dt_proj + softplus (K=48 zero-padded to 64)
    cvt(ssmp, ssh, ssl, MROWS, EPROJ, KPAD, RR);
    cvt(dtw,  dwh, dwl, II, RR, KPAD, RR);
    gemm_bf3<<<dim3(II / 128, MROWS / 128, 1), 256, GSMEM>>>(
        ssh, ssl, dwh, dwl, dt, dtb, II, KPAD, KPAD, II, KPAD / 32, 0, 1);

    // 5) selective scan with fused gating epilogue -> y (bf16 hi/lo)
    scan_kernel<<<dim3(II / 8, BSZ), 128>>>(
        dt, h, ssmp, proj, A_log, Dw, alpha, fg, yh, yl);

    // 6) out_proj: out[4096,768] = y @ outw^T  (K=1536, 48 iters)
    cvt(outw, owh, owl, DM, II, II, II);
    gemm_bf3<<<dim3(DM / 128, MROWS / 128, 1), 256, GSMEM>>>(
        yh, yl, owh, owl, out, nullptr, DM, II, II, DM, II / 32, 0, 0);
}

// round 6
// speedup vs baseline: 1.5025x; 1.2900x over previous
#include <cuda_runtime.h>
#include <math.h>
#include <stdint.h>

// Problem constants (B=2, S=2048, Dm=768, I=1536, N=16, R=48, K=4)
#define BSZ 2
#define SEQ 2048
#define DM 768
#define II 1536
#define NST 16
#define RR 48
#define MROWS (BSZ * SEQ)          // 4096
#define EPROJ 80                   // R + 2N
#define XSPLIT 8                   // split-K factor for x_proj
#define CH 8                       // scan chunk

// ---------------- scratch (no allocations allowed) ----------------
__device__ float g_proj [(size_t)MROWS * 2 * II];
__device__ float g_h    [(size_t)MROWS * II];
__device__ float g_ssmp [(size_t)MROWS * EPROJ];
__device__ float g_xpart[(size_t)XSPLIT * MROWS * EPROJ];
__device__ float g_dt   [(size_t)MROWS * II];
__device__ float g_y    [(size_t)MROWS * II];

// ---------------- packed f32x2 helpers ----------------
__device__ __forceinline__ unsigned long long pk2(float x) {
    unsigned long long r;
    asm("mov.b64 %0, {%1, %1};" : "=l"(r) : "f"(x));
    return r;
}
__device__ __forceinline__ void fma2(unsigned long long& c,
                                     unsigned long long a, unsigned long long b) {
    asm("fma.rn.f32x2 %0, %1, %2, %0;" : "+l"(c) : "l"(a), "l"(b));
}
__device__ __forceinline__ void upk2(unsigned long long v, float& lo, float& hi) {
    asm("mov.b64 {%0, %1}, %2;" : "=f"(lo), "=f"(hi) : "l"(v));
}

// ---------------- f32x2 SGEMM: C[M,N] = A[M,K] * B[N,K]^T ----------------
// 128x128x16 tile, 256 threads, SMEM stores A/B transposed [k][mn] (+4 pad),
// register-staged double buffer, packed-FFMA2 inner product.
// epi: 0 plain, 1 softplus(v + bias[n]). Split-K via blockIdx.z.
#define SPAD 132
__global__ __launch_bounds__(256, 2) void gemm_f32x2(
    const float* __restrict__ A, const float* __restrict__ B,
    float* __restrict__ C, const float* __restrict__ bias,
    int N, int lda, int ldb, int ldc, int nit, size_t cSlice, int epi)
{
    __shared__ __align__(16) float As[2][16][SPAD];
    __shared__ __align__(16) float Bs[2][16][SPAD];

    const int tid = threadIdx.x;
    const int tx = tid & 15, ty = tid >> 4;
    const int bm = blockIdx.y * 128;
    const int bn = blockIdx.x * 128;
    const int kOff = blockIdx.z * nit * 16;

    // loader mapping: row = (tid>>2) (+64), chunk = (tid&3)*4 floats along k
    const int lrow = tid >> 2;
    const int lc4 = (tid & 3) * 4;
    const float* pA = A + (size_t)(bm + lrow) * lda + kOff + lc4;
    const int brow0 = bn + lrow;
    const int brow1 = bn + lrow + 64;
    const bool bok0 = brow0 < N, bok1 = brow1 < N;
    const float* pB0 = B + (size_t)(bok0 ? brow0 : 0) * ldb + kOff + lc4;
    const float* pB1 = B + (size_t)(bok1 ? brow1 : 0) * ldb + kOff + lc4;

    unsigned long long acc[2][4][4];
#pragma unroll
    for (int ig = 0; ig < 2; ig++)
#pragma unroll
        for (int i = 0; i < 4; i++)
#pragma unroll
            for (int j = 0; j < 4; j++) acc[ig][i][j] = 0ull;

    float4 ra0, ra1, rb0, rb1;
    const float4 z4 = make_float4(0.f, 0.f, 0.f, 0.f);
    ra0 = *(const float4*)(pA);
    ra1 = *(const float4*)(pA + 64 * lda);
    rb0 = bok0 ? *(const float4*)(pB0) : z4;
    rb1 = bok1 ? *(const float4*)(pB1) : z4;

    for (int it = 0; it < nit; it++) {
        const int s = it & 1;
        // transpose-store staged regs into smem
        {
            float va[4] = {ra0.x, ra0.y, ra0.z, ra0.w};
            float vb[4] = {ra1.x, ra1.y, ra1.z, ra1.w};
            float vc[4] = {rb0.x, rb0.y, rb0.z, rb0.w};
            float vd[4] = {rb1.x, rb1.y, rb1.z, rb1.w};
#pragma unroll
            for (int j = 0; j < 4; j++) {
                As[s][lc4 + j][lrow]      = va[j];
                As[s][lc4 + j][lrow + 64] = vb[j];
                Bs[s][lc4 + j][lrow]      = vc[j];
                Bs[s][lc4 + j][lrow + 64] = vd[j];
            }
        }
        __syncthreads();
        // issue next-stage global loads before consuming this stage (overlap)
        if (it + 1 < nit) {
            const int kk = (it + 1) * 16;
            ra0 = *(const float4*)(pA + kk);
            ra1 = *(const float4*)(pA + 64 * lda + kk);
            rb0 = bok0 ? *(const float4*)(pB0 + kk) : z4;
            rb1 = bok1 ? *(const float4*)(pB1 + kk) : z4;
        }
#pragma unroll
        for (int k = 0; k < 16; k++) {
            const float4 a0 = *(const float4*)&As[s][k][ty * 4];
            const float4 a1 = *(const float4*)&As[s][k][ty * 4 + 64];
            const ulonglong2 b0 = *(const ulonglong2*)&Bs[s][k][tx * 4];
            const ulonglong2 b1 = *(const ulonglong2*)&Bs[s][k][tx * 4 + 64];
            float av[2][4] = {{a0.x, a0.y, a0.z, a0.w}, {a1.x, a1.y, a1.z, a1.w}};
#pragma unroll
            for (int ig = 0; ig < 2; ig++)
#pragma unroll
                for (int i = 0; i < 4; i++) {
                    const unsigned long long ap = pk2(av[ig][i]);
                    fma2(acc[ig][i][0], ap, b0.x);
                    fma2(acc[ig][i][1], ap, b0.y);
                    fma2(acc[ig][i][2], ap, b1.x);
                    fma2(acc[ig][i][3], ap, b1.y);
                }
        }
        __syncthreads();
    }

    // epilogue
    float* Co = C + (size_t)blockIdx.z * cSlice;
#pragma unroll
    for (int ig = 0; ig < 2; ig++)
#pragma unroll
        for (int i = 0; i < 4; i++) {
            const int gr = bm + ty * 4 + i + ig * 64;
#pragma unroll
            for (int j = 0; j < 4; j++) {
                const int gc = bn + tx * 4 + (j >> 1) * 64 + (j & 1) * 2;
                if (gc < N) {
                    float v0, v1;
                    upk2(acc[ig][i][j], v0, v1);
                    if (epi == 1) {
                        v0 += bias[gc];
                        v1 += bias[gc + 1];
                        v0 = (v0 > 20.f) ? v0 : log1pf(__expf(v0));
                        v1 = (v1 > 20.f) ? v1 : log1pf(__expf(v1));
                    }
                    Co[(size_t)gr * ldc + gc]     = v0;
                    Co[(size_t)gr * ldc + gc + 1] = v1;
                }
            }
        }
}

// ---------------- causal depthwise conv1d (K=4) + bias + SiLU ----------------
__global__ void conv_silu_kernel(const float* __restrict__ proj,
                                 const float* __restrict__ cw,
                                 const float* __restrict__ cb,
                                 float* __restrict__ h)
{
    const int idx = blockIdx.x * blockDim.x + threadIdx.x;
    if (idx >= BSZ * SEQ * II) return;
    const int i = idx % II;
    const int s = (idx / II) % SEQ;
    const int b = idx / (II * SEQ);
    const float* base = proj + (size_t)b * SEQ * 2 * II + i;
    float acc = cb[i];
#pragma unroll
    for (int k = 0; k < 4; k++) {
        const int sp = s - 3 + k;
        if (sp >= 0) acc = fmaf(base[(size_t)sp * 2 * II], cw[i * 4 + k], acc);
    }
    h[idx] = acc / (1.f + __expf(-acc));
}

// ---------------- split-K partial reduction (deterministic) ----------------
__global__ void reduceN_kernel(float* __restrict__ out,
                               const float* __restrict__ part, int n)
{
    const int idx = blockIdx.x * blockDim.x + threadIdx.x;
    if (idx >= n) return;
    float s = 0.f;
#pragma unroll
    for (int z = 0; z < XSPLIT; z++) s += part[(size_t)z * n + idx];
    out[idx] = s;
}

// ---------------- selective scan (chunked shfl) + fused epilogue ----------------
__global__ __launch_bounds__(128) void scan_kernel(
    const float* __restrict__ dt, const float* __restrict__ h,
    const float* __restrict__ ssmp, const float* __restrict__ proj,
    const float* __restrict__ A_log, const float* __restrict__ Dw,
    const float* __restrict__ alpha, const float* __restrict__ fg,
    float* __restrict__ Y)
{
    const int warp = threadIdx.x >> 5;
    const int lane = threadIdx.x & 31;
    const int grp  = lane >> 4;
    const int n    = lane & 15;
    const int i    = (blockIdx.x * 4 + warp) * 2 + grp;
    const int b    = blockIdx.y;

    const float Ai  = -__expf(A_log[i * NST + n]);
    const float Di  = Dw[i];
    const float al  = alpha[i];
    const float fgv = fg[i];

    const float* dtp = dt   + (size_t)b * SEQ * II + i;
    const float* hp  = h    + (size_t)b * SEQ * II + i;
    const float* bp  = ssmp + (size_t)b * SEQ * EPROJ + RR + n;
    const float* cp  = ssmp + (size_t)b * SEQ * EPROJ + RR + NST + n;
    const float* gp  = proj + (size_t)b * SEQ * 2 * II + II + i;
    float*       yp  = Y    + (size_t)b * SEQ * II + i;

    float state = 0.f;
    for (int s0 = 0; s0 < SEQ; s0 += CH) {
        float p[CH], hv[CH];
#pragma unroll
        for (int t = 0; t < CH; t++) {
            const int s = s0 + t;
            float dtv = dtp[(size_t)s * II];
            if (s == SEQ - 1) dtv *= al;
            hv[t] = hp[(size_t)s * II];
            const float Bv = bp[(size_t)s * EPROJ];
            const float Cv = cp[(size_t)s * EPROJ];
            const float dA = __expf(Ai * dtv);
            state = fmaf(dA, state, dtv * Bv * hv[t]);
            p[t] = state * Cv;
        }
#pragma unroll
        for (int lvl = 8; lvl >= 1; lvl >>= 1)
#pragma unroll
            for (int t = 0; t < CH; t++)
                p[t] += __shfl_xor_sync(0xffffffffu, p[t], lvl);
        if (n == 0) {
#pragma unroll
            for (int t = 0; t < CH; t++) {
                const int s = s0 + t;
                const float gv = gp[(size_t)s * 2 * II];
                const float sg = gv / (1.f + __expf(-gv));
                float yv = (p[t] + hv[t] * Di) * sg;
                if (s == SEQ - 1) yv *= fgv;
                yp[(size_t)s * II] = yv;
            }
        }
    }
}

// ---------------- launch ----------------
extern "C" void kernel_launch(void* const* d_in, const int* in_sizes, int n_in,
                              void* d_out, int out_size)
{
    const float* input   = (const float*)d_in[0];
    const float* inw     = (const float*)d_in[1];
    const float* convw   = (const float*)d_in[2];
    const float* convb   = (const float*)d_in[3];
    const float* xw      = (const float*)d_in[4];
    const float* dtw     = (const float*)d_in[5];
    const float* dtb     = (const float*)d_in[6];
    const float* A_log   = (const float*)d_in[7];
    const float* Dw      = (const float*)d_in[8];
    const float* outw    = (const float*)d_in[9];
    const float* alpha   = (const float*)d_in[10];
    const float* fg      = (const float*)d_in[11];
    float* out = (float*)d_out;

    float *proj, *h, *ssmp, *xpart, *dt, *y;
    cudaGetSymbolAddress((void**)&proj,  g_proj);
    cudaGetSymbolAddress((void**)&h,     g_h);
    cudaGetSymbolAddress((void**)&ssmp,  g_ssmp);
    cudaGetSymbolAddress((void**)&xpart, g_xpart);
    cudaGetSymbolAddress((void**)&dt,    g_dt);
    cudaGetSymbolAddress((void**)&y,     g_y);

    // 1) in_proj: proj[4096,3072] = input @ inw^T   (K=768, 48 iters)
    gemm_f32x2<<<dim3(2 * II / 128, MROWS / 128, 1), 256>>>(
        input, inw, proj, nullptr, 2 * II, DM, DM, 2 * II, DM / 16, 0, 0);

    // 2) depthwise conv + SiLU -> h
    {
        const int n = BSZ * SEQ * II;
        conv_silu_kernel<<<(n + 255) / 256, 256>>>(proj, convw, convb, h);
    }

    // 3) x_proj: ssmp[4096,80] = h @ xw^T  (split-K x8 + reduce)
    gemm_f32x2<<<dim3(1, MROWS / 128, XSPLIT), 256>>>(
        h, xw, xpart, nullptr, EPROJ, II, II, EPROJ,
        II / (XSPLIT * 16), (size_t)MROWS * EPROJ, 0);
    {
        const int n = MROWS * EPROJ;
        reduceN_kernel<<<(n + 255) / 256, 256>>>(ssmp, xpart, n);
    }

    // 4) dt_proj + softplus: dt[4096,1536] = softplus(ssmp[:,:48] @ dtw^T + b)
    gemm_f32x2<<<dim3(II / 128, MROWS / 128, 1), 256>>>(
        ssmp, dtw, dt, dtb, II, EPROJ, RR, II, RR / 16, 0, 1);

    // 5) selective scan with fused gating epilogue -> y
    scan_kernel<<<dim3(II / 8, BSZ), 128>>>(
        dt, h, ssmp, proj, A_log, Dw, alpha, fg, y);

    // 6) out_proj: out[4096,768] = y @ outw^T  (K=1536, 96 iters)
    gemm_f32x2<<<dim3(DM / 128, MROWS / 128, 1), 256>>>(
        y, outw, out, nullptr, DM, II, II, DM, II / 16, 0, 0);
}